// round 17
// baseline (speedup 1.0000x reference)
#include <cuda_runtime.h>
#include <cuda_bf16.h>
#include <cuda_fp16.h>
#include <math.h>

#define BATCH 4
#define SLEN  2048
#define HID   896
#define NH    14
#define NKV   2
#define HD    64
#define NREP  (NH / NKV)

typedef unsigned long long u64;
typedef unsigned int u32;
typedef unsigned short u16;

#define NA (8192 * 896)
#define NW (2048 * 896)
#define NQE (BATCH * NH * SLEN * HD)
#define NKE (BATCH * NKV * SLEN * HD)

// ---------------- scratch ----------------
__device__ float g_Q[NQE];              // fp32 post-GEMM Q (rope input)
__device__ float g_K[NKE];              // fp32 post-GEMM K (rope input)
__device__ u16 g_Ah[NA];                // hidden fp16
__device__ u16 g_Wh[NW];                // weights fp16
__device__ u16 g_Qh[NQE];               // roped Q*0.125*log2e, fp16
__device__ u16 g_Kh[NKE];               // roped K, fp16
__device__ u16 g_Vh[NKE];               // V, fp16
__device__ u16 g_Oh[NA];                // attn out fp16 (O-proj A operand)
__device__ float g_invf[HD / 2];

// ================= helpers =================
__device__ __forceinline__ u32 smem_u32(const void* p) {
    u32 a;
    asm("{ .reg .u64 t; cvta.to.shared.u64 t, %1; cvt.u32.u64 %0, t; }" : "=r"(a) : "l"(p));
    return a;
}
__device__ __forceinline__ void mma16816h(float* d, const u32* a, const u32* b) {
    asm volatile(
        "mma.sync.aligned.m16n8k16.row.col.f32.f16.f16.f32 "
        "{%0,%1,%2,%3}, {%4,%5,%6,%7}, {%8,%9}, {%0,%1,%2,%3};"
        : "+f"(d[0]), "+f"(d[1]), "+f"(d[2]), "+f"(d[3])
        : "r"(a[0]), "r"(a[1]), "r"(a[2]), "r"(a[3]), "r"(b[0]), "r"(b[1]));
}
__device__ __forceinline__ void ldsm4(u32* r, u32 addr) {
    asm volatile("ldmatrix.sync.aligned.m8n8.x4.shared.b16 {%0,%1,%2,%3}, [%4];"
                 : "=r"(r[0]), "=r"(r[1]), "=r"(r[2]), "=r"(r[3]) : "r"(addr));
}
__device__ __forceinline__ void ldsm4t(u32* r, u32 addr) {
    asm volatile("ldmatrix.sync.aligned.m8n8.x4.trans.shared.b16 {%0,%1,%2,%3}, [%4];"
                 : "=r"(r[0]), "=r"(r[1]), "=r"(r[2]), "=r"(r[3]) : "r"(addr));
}
__device__ __forceinline__ u32 pack2h(float x, float y) {
    __half2 h = __floats2half2_rn(x, y);
    return *(u32*)&h;
}
__device__ __forceinline__ u32 ex2h2(float x, float y) {
    u32 h, r;
    asm("cvt.rn.f16x2.f32 %0, %1, %2;" : "=r"(h) : "f"(y), "f"(x));
    asm("ex2.approx.f16x2 %0, %1;" : "=r"(r) : "r"(h));
    return r;
}
__device__ __forceinline__ float ex2f(float x) {
    float r;
    asm("ex2.approx.f32 %0, %1;" : "=f"(r) : "f"(x));
    return r;
}
__device__ __forceinline__ void cp16(u32 smem, const void* g) {
    asm volatile("cp.async.cg.shared.global [%0], [%1], 16;" :: "r"(smem), "l"(g));
}
#define CP_COMMIT() asm volatile("cp.async.commit_group;" ::: "memory")
#define CP_WAIT1()  asm volatile("cp.async.wait_group 1;" ::: "memory")

// ---------------- one-shot fp32 -> fp16 conversion (+ invf init in block 0) ----------------
__global__ void convert_kernel(const float* __restrict__ hs,
                               const float* __restrict__ Wq, const float* __restrict__ Wk,
                               const float* __restrict__ Wv, const float* __restrict__ Wo) {
    if (blockIdx.x == 0 && threadIdx.x < HD / 2) {
        g_invf[threadIdx.x] = (float)pow(1.0e6, -(double)threadIdx.x / 32.0);
    }
    const int idx = blockIdx.x * blockDim.x + threadIdx.x;
    const size_t f4 = (size_t)idx * 4;
    if (f4 < NA) {
        float4 v = *(const float4*)(hs + f4);
        *(uint2*)(g_Ah + f4) = make_uint2(pack2h(v.x, v.y), pack2h(v.z, v.w));
    } else {
        const size_t g = f4 - NA;
        if (g >= NW) return;
        const int row = (int)(g / 896);
        const float* src;
        if (row < 896)       src = Wq + g;
        else if (row < 1024) src = Wk + (g - (size_t)896 * 896);
        else if (row < 1152) src = Wv + (g - (size_t)1024 * 896);
        else                 src = Wo + (g - (size_t)1152 * 896);
        float4 v = *(const float4*)src;
        *(uint2*)(g_Wh + g) = make_uint2(pack2h(v.x, v.y), pack2h(v.z, v.w));
    }
}

// ============ GEMM: 128x128 tile, 8 warps (2m x 4n), single-term fp16, 2 CTAs/SM ============
#define G_STAGE 36864
#define G_SMEM  (2 * G_STAGE)

template <int IS_O>
__global__ __launch_bounds__(256, 2)
void tc_gemm(const float* __restrict__ bq, const float* __restrict__ bk,
             const float* __restrict__ bv, float* __restrict__ out)
{
    extern __shared__ char smraw[];
    const u32 smb = smem_u32(smraw);
    const int tid  = threadIdx.x;
    const int wid  = tid >> 5;
    const int lane = tid & 31;
    const int nb   = blockIdx.x;
    const int m0   = blockIdx.y * 128;

    const int wrow0 = IS_O ? (1152 + nb * 128) : (nb * 128);
    const u16* pAh = (IS_O ? g_Oh : g_Ah) + (size_t)m0 * 896;
    const u16* pBh = g_Wh + (size_t)wrow0 * 896;

    const int mbase = (wid & 1) * 64;
    const int nbase = (wid >> 1) * 32;

    const int g  = lane >> 3;
    const int l7 = lane & 7;
    const u32 aoffB = (u32)((mbase + (g & 1) * 8 + l7) * 72 + (g >> 1) * 8) * 2;
    const u32 boffB = (u32)((nbase + (g >> 1) * 8 + l7) * 72 + (g & 1) * 8) * 2;

    float acc[4][4][4];
#pragma unroll
    for (int i = 0; i < 4; ++i)
#pragma unroll
        for (int j = 0; j < 4; ++j)
#pragma unroll
            for (int k = 0; k < 4; ++k) acc[i][j][k] = 0.0f;

    auto issue = [&](int chunk, int s) {
        const u32 sb = smb + (u32)s * G_STAGE;
        const int kc0 = chunk * 64;
#pragma unroll
        for (int buf = 0; buf < 2; ++buf) {
            const u16* src = buf ? pBh : pAh;
#pragma unroll
            for (int t = 0; t < 4; ++t) {
                const int cc  = tid + t * 256;
                const int row = cc >> 3;
                const int col = cc & 7;
                cp16(sb + buf * 18432 + row * 144 + col * 16,
                     src + (size_t)row * 896 + kc0 + col * 8);
            }
        }
    };

    issue(0, 0);
    CP_COMMIT();

    for (int it = 0; it < 14; ++it) {
        if (it + 1 < 14) issue(it + 1, (it + 1) & 1);
        CP_COMMIT();
        CP_WAIT1();
        __syncthreads();

        const u32 stg = smb + (u32)(it & 1) * G_STAGE;
#pragma unroll
        for (int ks = 0; ks < 4; ++ks) {
            u32 ahi[4][4];
#pragma unroll
            for (int mi = 0; mi < 4; ++mi) {
                const u32 ad = stg + aoffB + (u32)(mi * 16 * 72) * 2 + ks * 32;
                ldsm4(ahi[mi], ad);
            }
            u32 bhi[4][2];
#pragma unroll
            for (int jp = 0; jp < 2; ++jp) {
                const u32 bd = stg + 18432 + boffB + (u32)(jp * 16 * 72) * 2 + ks * 32;
                u32 t4[4];
                ldsm4(t4, bd);
                bhi[2 * jp][0] = t4[0]; bhi[2 * jp][1] = t4[1];
                bhi[2 * jp + 1][0] = t4[2]; bhi[2 * jp + 1][1] = t4[3];
            }
#pragma unroll
            for (int mi = 0; mi < 4; ++mi)
#pragma unroll
                for (int nj = 0; nj < 4; ++nj)
                    mma16816h(acc[mi][nj], ahi[mi], bhi[nj]);
        }
        __syncthreads();
    }

    const int qrow = lane >> 2;
    const int qcol = (lane & 3) * 2;
#pragma unroll
    for (int mi = 0; mi < 4; ++mi) {
#pragma unroll
        for (int half = 0; half < 2; ++half) {
            const int r = mbase + mi * 16 + qrow + half * 8;
            const int m = m0 + r;
            const int bb = m >> 11;
            const int ss = m & (SLEN - 1);
#pragma unroll
            for (int nj = 0; nj < 4; ++nj) {
                const int col = nbase + nj * 8 + qcol;
                const float v0 = acc[mi][nj][half * 2];
                const float v1 = acc[mi][nj][half * 2 + 1];
                if (IS_O) {
                    float2 vv; vv.x = v0; vv.y = v1;
                    *(float2*)(out + (size_t)m * HID + nb * 128 + col) = vv;
                } else if (nb < 7) {
                    const int gc = nb * 128 + col;
                    const int h = gc >> 6, d0 = gc & 63;
                    float2 vv;
                    vv.x = v0 + bq[gc];
                    vv.y = v1 + bq[gc + 1];
                    *(float2*)(g_Q + (((size_t)(bb * NH + h)) * SLEN + ss) * HD + d0) = vv;
                } else if (nb == 7) {
                    const int h = col >> 6, d0 = col & 63;
                    float2 vv;
                    vv.x = v0 + bk[col];
                    vv.y = v1 + bk[col + 1];
                    *(float2*)(g_K + (((size_t)(bb * NKV + h)) * SLEN + ss) * HD + d0) = vv;
                } else {
                    const int h = col >> 6, d0 = col & 63;
                    const size_t off = (((size_t)(bb * NKV + h)) * SLEN + ss) * HD + d0;
                    *(u32*)(g_Vh + off) = pack2h(v0 + bv[col], v1 + bv[col + 1]);
                }
            }
        }
    }
}

// ---------------- RoPE: fp32 in; Q -> fp16 (x 0.125*log2e), K -> fp16 ----------------
#define QSCALE 0.18033688011112042f   // 0.125 * log2(e)

__global__ void rope_split_kernel(const int* __restrict__ pos_ids) {
    const int QROWS = BATCH * NH * SLEN;
    const int idx  = blockIdx.x * blockDim.x + threadIdx.x;
    const int pair = idx & 31;
    const int row  = idx >> 5;

    const int s = row & (SLEN - 1);
    const float p = (float)pos_ids[s];
    const float ang = p * g_invf[pair];
    float sn, cs;
    sincosf(ang, &sn, &cs);

    if (row < QROWS) {
        const float* base = g_Q + (size_t)row * HD;
        const float x1 = base[pair];
        const float x2 = base[pair + 32];
        const float y1 = (x1 * cs - x2 * sn) * QSCALE;
        const float y2 = (x2 * cs + x1 * sn) * QSCALE;
        u16* oh = g_Qh + (size_t)row * HD;
        __half h1 = __float2half_rn(y1);
        __half h2 = __float2half_rn(y2);
        oh[pair]      = *(u16*)&h1;
        oh[pair + 32] = *(u16*)&h2;
    } else {
        const int r2 = row - QROWS;
        const float* base = g_K + (size_t)r2 * HD;
        const float x1 = base[pair];
        const float x2 = base[pair + 32];
        const float y1 = x1 * cs - x2 * sn;
        const float y2 = x2 * cs + x1 * sn;
        u16* oh = g_Kh + (size_t)r2 * HD;
        __half h1 = __float2half_rn(y1);
        __half h2 = __float2half_rn(y2);
        oh[pair]      = *(u16*)&h1;
        oh[pair + 32] = *(u16*)&h2;
    }
}

// ---------------- Flash attention: 512 threads, n-split warp pairs ----------------
// smem: stages 2x36864 (Kh, Vh), rmbuf[2][128] @73728; obuf/lbuf reuse stage area post-loop.
#define F_STAGE 36864
#define F_RMOFF 73728
#define F_SMEM  (73728 + 1024)

__global__ __launch_bounds__(512, 1)
void flash_mma() {
    extern __shared__ char smraw[];
    const u32 smb = smem_u32(smraw);
    const int tid  = threadIdx.x;
    const int wid  = tid >> 5;
    const int lane = tid & 31;
    const int wq   = wid >> 1;   // 0..7: q-row group
    const int wn   = wid & 1;    // 0..1: n-half

    const int blk = (int)gridDim.x - 1 - (int)blockIdx.x;
    const int h   = blockIdx.y;
    const int b   = blockIdx.z;
    const int qi0 = blk * 128;
    const int kh  = h / NREP;

    const u16* Qh = g_Qh + ((size_t)(b * NH + h)) * SLEN * HD;
    const size_t kvoff = ((size_t)(b * NKV + kh)) * SLEN * HD;
    const u16* Kh = g_Kh + kvoff;
    const u16* Vh = g_Vh + kvoff;

    const int qr = lane >> 2;
    const int q2 = (lane & 3) * 2;
    const int row0 = qi0 + wq * 16 + qr;
    const int rloc0 = wq * 16 + qr;       // row within tile

    auto issue = [&](int jt, int s) {
        const u32 sb = smb + (u32)s * F_STAGE;
        const int k0 = jt * 128;
#pragma unroll
        for (int buf = 0; buf < 2; ++buf) {
            const u16* src = buf ? Vh : Kh;
#pragma unroll
            for (int t = 0; t < 2; ++t) {
                const int cc  = tid + t * 512;
                const int row = cc >> 3;
                const int col = cc & 7;
                cp16(sb + buf * 18432 + row * 144 + col * 16,
                     src + (size_t)(k0 + row) * HD + col * 8);
            }
        }
    };

    issue(0, 0);
    CP_COMMIT();

    u32 qhi[4][4];
#pragma unroll
    for (int kk = 0; kk < 4; ++kk) {
#pragma unroll
        for (int part = 0; part < 4; ++part) {
            const int r = row0 + (part & 1) * 8;
            const int c = kk * 16 + q2 + (part & 2) * 4;
            qhi[kk][part] = *(const u32*)(Qh + (size_t)r * HD + c);
        }
    }

    float o[8][4];
#pragma unroll
    for (int i = 0; i < 8; ++i)
#pragma unroll
        for (int c = 0; c < 4; ++c) o[i][c] = 0.0f;
    float mx[2] = {-1e30f, -1e30f};
    float l[2]  = {0.0f, 0.0f};

    const u32 ones2[2] = {0x3C003C00u, 0x3C003C00u};

    const int l7 = lane & 7;
    const int n_add = l7 + ((lane >> 4) & 1) * 8;
    const int k_add = ((lane >> 3) & 1) * 8;
    const int kv_add = l7 + ((lane >> 3) & 1) * 8;
    const int dv_add = ((lane >> 4) & 1) * 8;

    // rmbuf pointers
    float* rmbuf = (float*)(smraw + F_RMOFF);   // [2][128]

    for (int j = 0; j <= blk; ++j) {
        const int k0 = j * 128;
        if (j < blk) issue(j + 1, (j + 1) & 1);
        CP_COMMIT();
        CP_WAIT1();
        __syncthreads();

        const u32 stg = smb + (u32)(j & 1) * F_STAGE;

        // ---- S = Q*K^T (this warp's 64 cols) ----
        float sacc[8][4];
#pragma unroll
        for (int i = 0; i < 8; ++i)
#pragma unroll
            for (int c = 0; c < 4; ++c) sacc[i][c] = 0.0f;

#pragma unroll
        for (int kk = 0; kk < 4; ++kk) {
#pragma unroll
            for (int nbp = 0; nbp < 4; ++nbp) {
                const u32 ad = stg + (u32)((wn * 64 + nbp * 16 + n_add) * 72 + k_add) * 2 + kk * 32;
                u32 kh4[4];
                ldsm4(kh4, ad);
                mma16816h(sacc[2 * nbp],     qhi[kk], &kh4[0]);
                mma16816h(sacc[2 * nbp + 1], qhi[kk], &kh4[2]);
            }
        }

        // ---- causal mask ----
        if (j == blk) {
#pragma unroll
            for (int nb = 0; nb < 8; ++nb) {
                const int colb = k0 + wn * 64 + nb * 8 + q2;
#pragma unroll
                for (int c = 0; c < 4; ++c) {
                    const int col = colb + (c & 1);
                    const int row = row0 + (c >> 1) * 8;
                    if (col > row) sacc[nb][c] = -1e30f;
                }
            }
        }

        // ---- partial row max -> rmbuf ----
        float rmp[2];
#pragma unroll
        for (int hh = 0; hh < 2; ++hh) {
            float rm = -1e30f;
#pragma unroll
            for (int nb = 0; nb < 8; ++nb)
                rm = fmaxf(rm, fmaxf(sacc[nb][2 * hh], sacc[nb][2 * hh + 1]));
            rm = fmaxf(rm, __shfl_xor_sync(0xffffffffu, rm, 1));
            rm = fmaxf(rm, __shfl_xor_sync(0xffffffffu, rm, 2));
            rmp[hh] = rm;
            rmbuf[wn * 128 + rloc0 + hh * 8] = rm;
        }
        __syncthreads();

        // ---- combined max, corr, P, l, PV ----
        float mnew[2], corr[2];
#pragma unroll
        for (int hh = 0; hh < 2; ++hh) {
            const float other = rmbuf[(1 - wn) * 128 + rloc0 + hh * 8];
            mnew[hh] = fmaxf(mx[hh], fmaxf(rmp[hh], other));
            corr[hh] = ex2f(mx[hh] - mnew[hh]);
            mx[hh] = mnew[hh];
#pragma unroll
            for (int db = 0; db < 8; ++db) {
                o[db][2 * hh]     *= corr[hh];
                o[db][2 * hh + 1] *= corr[hh];
            }
        }

        u32 phi[4][4];
#pragma unroll
        for (int kk = 0; kk < 4; ++kk) {
            phi[kk][0] = ex2h2(sacc[2 * kk][0] - mnew[0],     sacc[2 * kk][1] - mnew[0]);
            phi[kk][1] = ex2h2(sacc[2 * kk][2] - mnew[1],     sacc[2 * kk][3] - mnew[1]);
            phi[kk][2] = ex2h2(sacc[2 * kk + 1][0] - mnew[0], sacc[2 * kk + 1][1] - mnew[0]);
            phi[kk][3] = ex2h2(sacc[2 * kk + 1][2] - mnew[1], sacc[2 * kk + 1][3] - mnew[1]);
        }

        {
            float lacc[4] = {0.0f, 0.0f, 0.0f, 0.0f};
#pragma unroll
            for (int kk = 0; kk < 4; ++kk)
                mma16816h(lacc, phi[kk], ones2);
            l[0] = l[0] * corr[0] + lacc[0];
            l[1] = l[1] * corr[1] + lacc[2];
        }

#pragma unroll
        for (int kk = 0; kk < 4; ++kk) {
#pragma unroll
            for (int dbp = 0; dbp < 4; ++dbp) {
                const u32 ad = stg + 18432 + (u32)((wn * 64 + kk * 16 + kv_add) * 72 + dbp * 16 + dv_add) * 2;
                u32 vh4[4];
                ldsm4t(vh4, ad);
                mma16816h(o[2 * dbp],     phi[kk], &vh4[0]);
                mma16816h(o[2 * dbp + 1], phi[kk], &vh4[2]);
            }
        }
        __syncthreads();
    }

    // ---- cross-warp-pair reduction of O and l (reuse stage smem) ----
    float* obuf = (float*)smraw;            // [128][64]
    float* lbuf = (float*)(smraw + 32768);  // [128]
    if (wn == 1) {
#pragma unroll
        for (int hh = 0; hh < 2; ++hh) {
            const int rl = rloc0 + hh * 8;
#pragma unroll
            for (int db = 0; db < 8; ++db) {
                float2 vv;
                vv.x = o[db][2 * hh];
                vv.y = o[db][2 * hh + 1];
                *(float2*)&obuf[rl * 64 + db * 8 + q2] = vv;
            }
            if ((lane & 3) == 0) lbuf[rl] = l[hh];
        }
    }
    __syncthreads();
    if (wn == 0) {
#pragma unroll
        for (int hh = 0; hh < 2; ++hh) {
            const int rl = rloc0 + hh * 8;
            const float inv = 1.0f / (l[hh] + lbuf[rl]);
            const int row = row0 + hh * 8;
            const size_t rb = ((size_t)(b * SLEN) + row) * (NH * HD) + h * HD;
#pragma unroll
            for (int db = 0; db < 8; ++db) {
                float2 pp = *(float2*)&obuf[rl * 64 + db * 8 + q2];
                *(u32*)(g_Oh + rb + db * 8 + q2) =
                    pack2h((o[db][2 * hh] + pp.x) * inv,
                           (o[db][2 * hh + 1] + pp.y) * inv);
            }
        }
    }
}

// ---------------- launch ----------------
extern "C" void kernel_launch(void* const* d_in, const int* in_sizes, int n_in,
                              void* d_out, int out_size) {
    const float* hs  = (const float*)d_in[0];
    const int*   pos = (const int*)d_in[1];
    const float* Wq  = (const float*)d_in[2];
    const float* bq  = (const float*)d_in[3];
    const float* Wk  = (const float*)d_in[4];
    const float* bk  = (const float*)d_in[5];
    const float* Wv  = (const float*)d_in[6];
    const float* bv  = (const float*)d_in[7];
    const float* Wo  = (const float*)d_in[8];
    float* out = (float*)d_out;

    (void)in_sizes; (void)n_in; (void)out_size;

    cudaFuncSetAttribute(tc_gemm<0>, cudaFuncAttributeMaxDynamicSharedMemorySize, G_SMEM);
    cudaFuncSetAttribute(tc_gemm<1>, cudaFuncAttributeMaxDynamicSharedMemorySize, G_SMEM);
    cudaFuncSetAttribute(flash_mma, cudaFuncAttributeMaxDynamicSharedMemorySize, F_SMEM);

    convert_kernel<<<(NA + NW) / 4 / 256, 256>>>(hs, Wq, Wk, Wv, Wo);

    // fused QKV projection: nb 0..6 Q, 7 K, 8 V
    tc_gemm<0><<<dim3(9, 64), 256, G_SMEM>>>(bq, bk, bv, nullptr);

    {
        const int qrows = BATCH * NH * SLEN;
        const int krows = BATCH * NKV * SLEN;
        const int total = (qrows + krows) * (HD / 2);
        rope_split_kernel<<<total / 256, 256>>>(pos);
    }

    flash_mma<<<dim3(SLEN / 128, NH, BATCH), 512, F_SMEM>>>();

    // O projection -> d_out
    tc_gemm<1><<<dim3(7, 64), 256, G_SMEM>>>(nullptr, nullptr, nullptr, out);
}